// round 7
// baseline (speedup 1.0000x reference)
#include <cuda_runtime.h>
#include <cstdint>

#define NN 50000
#define NE 640000

__device__ float g_agg[(size_t)NN * 128];
__device__ float g_U[(size_t)NN * 128];    // node_h @ We1[0:128]
__device__ float g_V[(size_t)NN * 128];    // node_h @ We1[128:256]
__device__ float g_P[(size_t)NN * 128];    // node_h @ Wn1[128:256]
// weight slab images, transposed [128 N x 64 K] bf16 row-major (128B/row):
// We1:0-5, We2:6-7, Wn1:8-11, Wn2:12-13
__device__ __align__(16) unsigned char g_Wh[14 * 16384];
__device__ __align__(16) unsigned char g_Wl[14 * 16384];

static __device__ __forceinline__ uint32_t smem_u32(const void* p) {
    uint32_t a;
    asm("{ .reg .u64 t; cvta.to.shared.u64 t, %1; cvt.u32.u64 %0, t; }" : "=r"(a) : "l"(p));
    return a;
}
static __device__ __forceinline__ uint32_t prmt_hi16(uint32_t a, uint32_t b) {
    uint32_t r; asm("prmt.b32 %0,%1,%2,0x7632;" : "=r"(r) : "r"(a), "r"(b)); return r;
}
static __device__ __forceinline__ float trh(float x) {
    return __uint_as_float(__float_as_uint(x) & 0xFFFF0000u);
}
static __device__ __forceinline__ uint32_t bf2(float hi_, float lo_) {
    uint32_t r; asm("cvt.rn.bf16x2.f32 %0,%1,%2;" : "=r"(r) : "f"(hi_), "f"(lo_)); return r;
}

#define CPA(dst, src) asm volatile("cp.async.ca.shared.global [%0], [%1], 16;" :: "r"(dst), "l"(src))
#define CPC()         asm volatile("cp.async.commit_group;" ::: "memory")
#define CPW(n)        asm volatile("cp.async.wait_group %0;" :: "n"(n) : "memory")

static __device__ __forceinline__ void ldsm4(uint32_t addr, uint32_t* r) {
    asm volatile("ldmatrix.sync.aligned.m8n8.x4.shared.b16 {%0,%1,%2,%3}, [%4];"
                 : "=r"(r[0]), "=r"(r[1]), "=r"(r[2]), "=r"(r[3]) : "r"(addr));
}
static __device__ __forceinline__ void mma16816(float* d, const uint32_t* a, const uint32_t* b) {
    asm volatile("mma.sync.aligned.m16n8k16.row.col.f32.bf16.bf16.f32 "
                 "{%0,%1,%2,%3},{%4,%5,%6,%7},{%8,%9},{%0,%1,%2,%3};"
                 : "+f"(d[0]), "+f"(d[1]), "+f"(d[2]), "+f"(d[3])
                 : "r"(a[0]), "r"(a[1]), "r"(a[2]), "r"(a[3]), "r"(b[0]), "r"(b[1]));
}

// SMEM layout
#define OFF_DST  0
#define OFF_ROWS 512
#define BUF      18432
#define OFF_AH(b) (2048 + (b) * BUF)            // AH0,AH1 contiguous (Y reuse)
#define OFF_AL(b) (2048 + 2 * BUF + (b) * BUF)
#define OFF_BH(b) (2048 + 4 * BUF + (b) * BUF)
#define OFF_BL(b) (2048 + 6 * BUF + (b) * BUF)
#define SM_BYTES  (2048 + 8 * BUF)
#define ASTR 144
#define YSTR 272

#define ZACC(a) do {                                                   \
    _Pragma("unroll") for (int _m = 0; _m < 2; _m++)                   \
    _Pragma("unroll") for (int _n = 0; _n < 8; _n++)                   \
    _Pragma("unroll") for (int _q = 0; _q < 4; _q++) (a)[_m][_n][_q] = 0.f; } while (0)

// one K=16 chunk, 3-term compensated: 12 LDSM + 48 MMA
static __device__ __forceinline__ void mma_chunk(
        uint32_t ahb, uint32_t alb, int astride,
        uint32_t bhb, uint32_t blb,
        int mrow, int nbase, int kb, int bkb, int lane, float acc[2][8][4]) {
    uint32_t ah[2][4], al[2][4], bh[4][4], bl[4][4];
    const int arow = mrow + (lane & 15);
    const int ak   = kb + (lane >> 4) * 16;
#pragma unroll
    for (int mt = 0; mt < 2; mt++) {
        uint32_t off = (uint32_t)((arow + 16 * mt) * astride + ak);
        ldsm4(ahb + off, ah[mt]);
        ldsm4(alb + off, al[mt]);
    }
    const int bn = (lane & 7) + 8 * (lane >> 4);
    const int bk = bkb + ((lane >> 3) & 1) * 16;
#pragma unroll
    for (int nt2 = 0; nt2 < 4; nt2++) {
        uint32_t off = (uint32_t)((nbase + 16 * nt2 + bn) * ASTR + bk);
        ldsm4(bhb + off, bh[nt2]);
        ldsm4(blb + off, bl[nt2]);
    }
#pragma unroll
    for (int mt = 0; mt < 2; mt++)
#pragma unroll
        for (int nt = 0; nt < 8; nt++) {
            const uint32_t* bhp = &bh[nt >> 1][2 * (nt & 1)];
            const uint32_t* blp = &bl[nt >> 1][2 * (nt & 1)];
            mma16816(acc[mt][nt], ah[mt], bhp);
            mma16816(acc[mt][nt], ah[mt], blp);
            mma16816(acc[mt][nt], al[mt], bhp);
        }
}

static __device__ __forceinline__ void load_W(uint32_t sb, int oh, int ol, int slab, int tid) {
    for (int u = tid; u < 2048; u += 256) {
        int isLo = u >> 10, uu = u & 1023, r = uu >> 3, c = uu & 7;
        const unsigned char* g = (isLo ? g_Wl : g_Wh) + slab * 16384;
        CPA(sb + (isLo ? ol : oh) + r * ASTR + c * 16, g + r * 128 + c * 16);
    }
}
static __device__ __forceinline__ void load_f32split(unsigned char* sm, int oh, int ol,
        const float* base, const int* rows, int rbase, int koff, int tid) {
    for (int u = tid; u < 2048; u += 256) {
        int r = u >> 4, c4 = u & 15;
        size_t row = rows ? (size_t)rows[r] : (size_t)(rbase + r);
        float4 v = *(const float4*)(base + row * 128 + koff + c4 * 4);
        uint2 hi, lo;
        hi.x = prmt_hi16(__float_as_uint(v.x), __float_as_uint(v.y));
        hi.y = prmt_hi16(__float_as_uint(v.z), __float_as_uint(v.w));
        lo.x = bf2(v.y - trh(v.y), v.x - trh(v.x));
        lo.y = bf2(v.w - trh(v.w), v.z - trh(v.z));
        *(uint2*)(sm + oh + r * ASTR + c4 * 8) = hi;
        *(uint2*)(sm + ol + r * ASTR + c4 * 8) = lo;
    }
}

// ---- prep kernels ----
__global__ void zero_agg_kernel() {
    size_t stride = (size_t)gridDim.x * blockDim.x * 4;
    for (size_t i = (size_t)(blockIdx.x * blockDim.x + threadIdx.x) * 4;
         i < (size_t)NN * 128; i += stride)
        *(float4*)&g_agg[i] = make_float4(0.f, 0.f, 0.f, 0.f);
}
__global__ void prep_weights_kernel(const float* __restrict__ We1, const float* __restrict__ We2,
                                    const float* __restrict__ Wn1, const float* __restrict__ Wn2) {
    int s = blockIdx.x;
    const float* W; int slab;
    if (s < 6)       { W = We1; slab = s; }
    else if (s < 8)  { W = We2; slab = s - 6; }
    else if (s < 12) { W = Wn1; slab = s - 8; }
    else             { W = Wn2; slab = s - 12; }
    unsigned char* ph = g_Wh + s * 16384;
    unsigned char* pl = g_Wl + s * 16384;
    int k0 = slab * 64;
    for (int p = threadIdx.x; p < 4096; p += blockDim.x) {
        int n = p >> 5, kk = (p & 31) << 1;
        float x0 = W[(size_t)(k0 + kk) * 128 + n];
        float x1 = W[(size_t)(k0 + kk + 1) * 128 + n];
        *(uint32_t*)(ph + n * 128 + kk * 2) = prmt_hi16(__float_as_uint(x0), __float_as_uint(x1));
        *(uint32_t*)(pl + n * 128 + kk * 2) = bf2(x1 - trh(x1), x0 - trh(x0));
    }
}

// ---- precompute: U = nh@We1[0:128], V = nh@We1[128:256], P = nh@Wn1[128:256] ----
__global__ __launch_bounds__(256, 1)
void precompute_kernel(const float* __restrict__ node_h) {
    extern __shared__ __align__(1024) unsigned char sm[];
    const uint32_t sb = smem_u32(sm);
    const int tid = threadIdx.x, wid = tid >> 5, lane = tid & 31;
    const int nbase0 = blockIdx.x << 7;
    const int mrow = (wid >> 1) << 5;
    const int nbase = (wid & 1) << 6;

    int* rowsS = (int*)(sm + OFF_ROWS);
    if (tid < 128) { int n = nbase0 + tid; if (n >= NN) n = NN - 1; rowsS[tid] = n; }
    __syncthreads();

    load_f32split(sm, OFF_AH(0), OFF_AL(0), node_h, rowsS, 0, 0, tid);
    load_f32split(sm, OFF_AH(1), OFF_AL(1), node_h, rowsS, 0, 64, tid);

    const int ra = mrow + (lane >> 2);
    const int cc = nbase + 2 * (lane & 3);
    const int w0[3] = {0, 2, 10}, w1[3] = {1, 3, 11};
    float* outs[3] = {g_U, g_V, g_P};
#pragma unroll 1
    for (int t = 0; t < 3; t++) {
        load_W(sb, OFF_BH(0), OFF_BL(0), w0[t], tid);
        load_W(sb, OFF_BH(1), OFF_BL(1), w1[t], tid);
        CPC(); CPW(0);
        __syncthreads();
        float acc[2][8][4]; ZACC(acc);
        for (int c = 0; c < 4; c++)
            mma_chunk(sb + OFF_AH(0), sb + OFF_AL(0), ASTR, sb + OFF_BH(0), sb + OFF_BL(0),
                      mrow, nbase, c * 32, c * 32, lane, acc);
        for (int c = 0; c < 4; c++)
            mma_chunk(sb + OFF_AH(1), sb + OFF_AL(1), ASTR, sb + OFF_BH(1), sb + OFF_BL(1),
                      mrow, nbase, c * 32, c * 32, lane, acc);
        __syncthreads();
        float* op = outs[t];
#pragma unroll
        for (int mt = 0; mt < 2; mt++)
#pragma unroll
            for (int h = 0; h < 2; h++) {
                int r = ra + 16 * mt + 8 * h;
                int n = nbase0 + r;
                if (n < NN) {
#pragma unroll
                    for (int nt = 0; nt < 8; nt++) {
                        int c = cc + 8 * nt;
                        *(float2*)(op + (size_t)n * 128 + c) =
                            make_float2(acc[mt][nt][2 * h], acc[mt][nt][2 * h + 1]);
                    }
                }
            }
    }
}

// ---- edge kernel: y2 = (relu(U[src]+V[dst]+e@Wc+be1))@We2+be2 -> atomic agg ----
__global__ __launch_bounds__(256, 1)
void edge_kernel(const float* __restrict__ edge_h,
                 const int* __restrict__ src, const int* __restrict__ dst,
                 const float* __restrict__ be1, const float* __restrict__ be2) {
    extern __shared__ __align__(1024) unsigned char sm[];
    const uint32_t sb = smem_u32(sm);
    const int tid = threadIdx.x, wid = tid >> 5, lane = tid & 31;
    const int ebase = blockIdx.x << 7;
    const int mrow = (wid >> 1) << 5;
    const int nbase = (wid & 1) << 6;

    int* srcS = (int*)(sm + OFF_ROWS);
    int* dstS = (int*)(sm + OFF_DST);
    if (tid < 128) { srcS[tid] = src[ebase + tid]; dstS[tid] = dst[ebase + tid]; }
    __syncthreads();

    load_f32split(sm, OFF_AH(0), OFF_AL(0), edge_h, nullptr, ebase, 0, tid);
    load_W(sb, OFF_BH(0), OFF_BL(0), 4, tid); CPC();             // g1
    load_f32split(sm, OFF_AH(1), OFF_AL(1), edge_h, nullptr, ebase, 64, tid);
    load_W(sb, OFF_BH(1), OFF_BL(1), 5, tid); CPC();             // g2

    float acc[2][8][4]; ZACC(acc);
    CPW(1);                       // g1 done
    __syncthreads();
    for (int c = 0; c < 4; c++)
        mma_chunk(sb + OFF_AH(0), sb + OFF_AL(0), ASTR, sb + OFF_BH(0), sb + OFF_BL(0),
                  mrow, nbase, c * 32, c * 32, lane, acc);
    __syncthreads();
    load_W(sb, OFF_BH(0), OFF_BL(0), 6, tid); CPC();             // g3 = We2 k0
    CPW(1);                       // g2 done
    __syncthreads();
    for (int c = 0; c < 4; c++)
        mma_chunk(sb + OFF_AH(1), sb + OFF_AL(1), ASTR, sb + OFF_BH(1), sb + OFF_BL(1),
                  mrow, nbase, c * 32, c * 32, lane, acc);
    __syncthreads();
    load_W(sb, OFF_BH(1), OFF_BL(1), 7, tid); CPC();             // g4 = We2 k64

    // epilogue1: acc + U[src] + V[dst] + be1 -> relu -> split -> Y
    const int ra = mrow + (lane >> 2);
    const int cc = nbase + 2 * (lane & 3);
    float2 bia[8];
#pragma unroll
    for (int nt = 0; nt < 8; nt++)
        bia[nt] = make_float2(__ldg(&be1[cc + 8 * nt]), __ldg(&be1[cc + 8 * nt + 1]));
#pragma unroll
    for (int mt = 0; mt < 2; mt++)
#pragma unroll
        for (int h = 0; h < 2; h++) {
            int r = ra + 16 * mt + 8 * h;
            const float* up = g_U + (size_t)srcS[r] * 128;
            const float* vp = g_V + (size_t)dstS[r] * 128;
#pragma unroll
            for (int nt = 0; nt < 8; nt++) {
                int c = cc + 8 * nt;
                float2 u = __ldg((const float2*)(up + c));
                float2 v = __ldg((const float2*)(vp + c));
                float v0 = fmaxf(acc[mt][nt][2 * h]     + u.x + v.x + bia[nt].x, 0.f);
                float v1 = fmaxf(acc[mt][nt][2 * h + 1] + u.y + v.y + bia[nt].y, 0.f);
                *(uint32_t*)(sm + OFF_AH(0) + r * YSTR + c * 2) =
                    prmt_hi16(__float_as_uint(v0), __float_as_uint(v1));
                *(uint32_t*)(sm + OFF_AL(0) + r * YSTR + c * 2) =
                    bf2(v1 - trh(v1), v0 - trh(v0));
            }
        }
    ZACC(acc);
    CPW(0);
    __syncthreads();

    // GEMM2: Y(K=128) @ We2
    for (int c = 0; c < 8; c++)
        mma_chunk(sb + OFF_AH(0), sb + OFF_AL(0), YSTR,
                  sb + OFF_BH(c >> 2), sb + OFF_BL(c >> 2),
                  mrow, nbase, c * 32, (c & 3) * 32, lane, acc);

    // epilogue2: + be2, scatter-add
#pragma unroll
    for (int nt = 0; nt < 8; nt++)
        bia[nt] = make_float2(__ldg(&be2[cc + 8 * nt]), __ldg(&be2[cc + 8 * nt + 1]));
#pragma unroll
    for (int mt = 0; mt < 2; mt++)
#pragma unroll
        for (int h = 0; h < 2; h++) {
            int r = ra + 16 * mt + 8 * h;
            float* gp = g_agg + (size_t)dstS[r] * 128;
#pragma unroll
            for (int nt = 0; nt < 8; nt++) {
                int c = cc + 8 * nt;
                atomicAdd(gp + c,     acc[mt][nt][2 * h]     + bia[nt].x);
                atomicAdd(gp + c + 1, acc[mt][nt][2 * h + 1] + bia[nt].y);
            }
        }
}

// ---- node kernel: out = relu(agg@Wn1a + P + bn1)@Wn2 + bn2 ----
__global__ __launch_bounds__(256, 1)
void node_kernel(const float* __restrict__ bn1, const float* __restrict__ bn2,
                 float* __restrict__ out) {
    extern __shared__ __align__(1024) unsigned char sm[];
    const uint32_t sb = smem_u32(sm);
    const int tid = threadIdx.x, wid = tid >> 5, lane = tid & 31;
    const int nbase0 = blockIdx.x << 7;
    const int mrow = (wid >> 1) << 5;
    const int nbase = (wid & 1) << 6;

    int* rowsS = (int*)(sm + OFF_ROWS);
    if (tid < 128) { int n = nbase0 + tid; if (n >= NN) n = NN - 1; rowsS[tid] = n; }
    __syncthreads();

    load_f32split(sm, OFF_AH(0), OFF_AL(0), g_agg, rowsS, 0, 0, tid);
    load_W(sb, OFF_BH(0), OFF_BL(0), 8, tid); CPC();
    load_f32split(sm, OFF_AH(1), OFF_AL(1), g_agg, rowsS, 0, 64, tid);
    load_W(sb, OFF_BH(1), OFF_BL(1), 9, tid); CPC();

    float acc[2][8][4]; ZACC(acc);
    CPW(1);
    __syncthreads();
    for (int c = 0; c < 4; c++)
        mma_chunk(sb + OFF_AH(0), sb + OFF_AL(0), ASTR, sb + OFF_BH(0), sb + OFF_BL(0),
                  mrow, nbase, c * 32, c * 32, lane, acc);
    __syncthreads();
    load_W(sb, OFF_BH(0), OFF_BL(0), 12, tid); CPC();
    CPW(1);
    __syncthreads();
    for (int c = 0; c < 4; c++)
        mma_chunk(sb + OFF_AH(1), sb + OFF_AL(1), ASTR, sb + OFF_BH(1), sb + OFF_BL(1),
                  mrow, nbase, c * 32, c * 32, lane, acc);
    __syncthreads();
    load_W(sb, OFF_BH(1), OFF_BL(1), 13, tid); CPC();

    const int ra = mrow + (lane >> 2);
    const int cc = nbase + 2 * (lane & 3);
    float2 bia[8];
#pragma unroll
    for (int nt = 0; nt < 8; nt++)
        bia[nt] = make_float2(__ldg(&bn1[cc + 8 * nt]), __ldg(&bn1[cc + 8 * nt + 1]));
#pragma unroll
    for (int mt = 0; mt < 2; mt++)
#pragma unroll
        for (int h = 0; h < 2; h++) {
            int r = ra + 16 * mt + 8 * h;
            const float* pp = g_P + (size_t)rowsS[r] * 128;
#pragma unroll
            for (int nt = 0; nt < 8; nt++) {
                int c = cc + 8 * nt;
                float2 p = __ldg((const float2*)(pp + c));
                float v0 = fmaxf(acc[mt][nt][2 * h]     + p.x + bia[nt].x, 0.f);
                float v1 = fmaxf(acc[mt][nt][2 * h + 1] + p.y + bia[nt].y, 0.f);
                *(uint32_t*)(sm + OFF_AH(0) + r * YSTR + c * 2) =
                    prmt_hi16(__float_as_uint(v0), __float_as_uint(v1));
                *(uint32_t*)(sm + OFF_AL(0) + r * YSTR + c * 2) =
                    bf2(v1 - trh(v1), v0 - trh(v0));
            }
        }
    ZACC(acc);
    CPW(0);
    __syncthreads();

    for (int c = 0; c < 8; c++)
        mma_chunk(sb + OFF_AH(0), sb + OFF_AL(0), YSTR,
                  sb + OFF_BH(c >> 2), sb + OFF_BL(c >> 2),
                  mrow, nbase, c * 32, (c & 3) * 32, lane, acc);

#pragma unroll
    for (int nt = 0; nt < 8; nt++)
        bia[nt] = make_float2(__ldg(&bn2[cc + 8 * nt]), __ldg(&bn2[cc + 8 * nt + 1]));
#pragma unroll
    for (int mt = 0; mt < 2; mt++)
#pragma unroll
        for (int h = 0; h < 2; h++) {
            int r = ra + 16 * mt + 8 * h;
            int n = nbase0 + r;
            if (n < NN) {
#pragma unroll
                for (int nt = 0; nt < 8; nt++) {
                    int c = cc + 8 * nt;
                    *(float2*)(out + (size_t)n * 128 + c) =
                        make_float2(acc[mt][nt][2 * h]     + bia[nt].x,
                                    acc[mt][nt][2 * h + 1] + bia[nt].y);
                }
            }
        }
}

extern "C" void kernel_launch(void* const* d_in, const int* in_sizes, int n_in,
                              void* d_out, int out_size) {
    const float* node_h = (const float*)d_in[0];
    const float* edge_h = (const float*)d_in[1];
    const int*   src    = (const int*)d_in[2];
    const int*   dst    = (const int*)d_in[3];
    const float* We1    = (const float*)d_in[4];
    const float* be1    = (const float*)d_in[5];
    const float* We2    = (const float*)d_in[6];
    const float* be2    = (const float*)d_in[7];
    const float* Wn1    = (const float*)d_in[8];
    const float* bn1    = (const float*)d_in[9];
    const float* Wn2    = (const float*)d_in[10];
    const float* bn2    = (const float*)d_in[11];
    float* out = (float*)d_out;

    cudaFuncSetAttribute(precompute_kernel, cudaFuncAttributeMaxDynamicSharedMemorySize, SM_BYTES);
    cudaFuncSetAttribute(edge_kernel, cudaFuncAttributeMaxDynamicSharedMemorySize, SM_BYTES);
    cudaFuncSetAttribute(node_kernel, cudaFuncAttributeMaxDynamicSharedMemorySize, SM_BYTES);

    zero_agg_kernel<<<1024, 256>>>();
    prep_weights_kernel<<<14, 256>>>(We1, We2, Wn1, Wn2);
    precompute_kernel<<<(NN + 127) / 128, 256, SM_BYTES>>>(node_h);
    edge_kernel<<<NE / 128, 256, SM_BYTES>>>(edge_h, src, dst, be1, be2);
    node_kernel<<<(NN + 127) / 128, 256, SM_BYTES>>>(bn1, bn2, out);
}

// round 8
// speedup vs baseline: 1.6257x; 1.6257x over previous
#include <cuda_runtime.h>
#include <cstdint>

#define NN 50000
#define NE 640000

__device__ float g_agg[(size_t)NN * 128];
__device__ __align__(16) unsigned short g_nhi[(size_t)NN * 128];
__device__ __align__(16) unsigned short g_nlo[(size_t)NN * 128];
// weight slab images, transposed [128 N x 64 K] bf16 row-major (128B/row):
// We1:0-5, We2:6-7, Wn1:8-11, Wn2:12-13
__device__ __align__(16) unsigned char g_Wh[14 * 16384];
__device__ __align__(16) unsigned char g_Wl[14 * 16384];

static __device__ __forceinline__ uint32_t smem_u32(const void* p) {
    uint32_t a;
    asm("{ .reg .u64 t; cvta.to.shared.u64 t, %1; cvt.u32.u64 %0, t; }" : "=r"(a) : "l"(p));
    return a;
}
static __device__ __forceinline__ uint32_t prmt_hi16(uint32_t a, uint32_t b) {
    uint32_t r; asm("prmt.b32 %0,%1,%2,0x7632;" : "=r"(r) : "r"(a), "r"(b)); return r;
}
static __device__ __forceinline__ float trh(float x) {
    return __uint_as_float(__float_as_uint(x) & 0xFFFF0000u);
}
static __device__ __forceinline__ uint32_t bf2(float hi_, float lo_) {
    uint32_t r; asm("cvt.rn.bf16x2.f32 %0,%1,%2;" : "=r"(r) : "f"(hi_), "f"(lo_)); return r;
}

#define CPA(dst, src) asm volatile("cp.async.ca.shared.global [%0], [%1], 16;" :: "r"(dst), "l"(src))
#define CPC()         asm volatile("cp.async.commit_group;" ::: "memory")
#define CPW(n)        asm volatile("cp.async.wait_group %0;" :: "n"(n) : "memory")

static __device__ __forceinline__ void ldsm4(uint32_t addr, uint32_t* r) {
    asm volatile("ldmatrix.sync.aligned.m8n8.x4.shared.b16 {%0,%1,%2,%3}, [%4];"
                 : "=r"(r[0]), "=r"(r[1]), "=r"(r[2]), "=r"(r[3]) : "r"(addr));
}
static __device__ __forceinline__ void mma16816(float* d, const uint32_t* a, const uint32_t* b) {
    asm volatile("mma.sync.aligned.m16n8k16.row.col.f32.bf16.bf16.f32 "
                 "{%0,%1,%2,%3},{%4,%5,%6,%7},{%8,%9},{%0,%1,%2,%3};"
                 : "+f"(d[0]), "+f"(d[1]), "+f"(d[2]), "+f"(d[3])
                 : "r"(a[0]), "r"(a[1]), "r"(a[2]), "r"(a[3]), "r"(b[0]), "r"(b[1]));
}

// SMEM: 64-row A tiles (hi/lo, double-buffered) + 128-row B (hi/lo, single)
#define OFF_DST  0
#define OFF_ROWS 256
#define ABUF     9216                     // 64 * 144
#define OFF_AH(b) (2048 + (b) * ABUF)     // AH0,AH1 contiguous (Y hi reuse)
#define OFF_AL(b) (2048 + 2 * ABUF + (b) * ABUF)
#define OFF_BH    (2048 + 4 * ABUF)       // 128 * 144 = 18432
#define OFF_BL    (OFF_BH + 18432)
#define SM_BYTES  (2048 + 4 * ABUF + 2 * 18432)   // 75776
#define ASTR 144
#define YSTR 272

#define ZACC(a) do {                                                   \
    _Pragma("unroll") for (int _m = 0; _m < 2; _m++)                   \
    _Pragma("unroll") for (int _n = 0; _n < 8; _n++)                   \
    _Pragma("unroll") for (int _q = 0; _q < 4; _q++) (a)[_m][_n][_q] = 0.f; } while (0)

// one K=16 chunk, 3-term compensated: 12 LDSM + 48 MMA (per warp: 32 rows x 64 cols)
static __device__ __forceinline__ void mma_chunk(
        uint32_t ahb, uint32_t alb, int astride, uint32_t bhb, uint32_t blb,
        int mrow, int nbase, int kb, int bkb, int lane, float acc[2][8][4]) {
    uint32_t ah[2][4], al[2][4], bh[4][4], bl[4][4];
    const int arow = mrow + (lane & 15);
    const int ak   = kb + (lane >> 4) * 16;
#pragma unroll
    for (int mt = 0; mt < 2; mt++) {
        uint32_t off = (uint32_t)((arow + 16 * mt) * astride + ak);
        ldsm4(ahb + off, ah[mt]);
        ldsm4(alb + off, al[mt]);
    }
    const int bn = (lane & 7) + 8 * (lane >> 4);
    const int bk = bkb + ((lane >> 3) & 1) * 16;
#pragma unroll
    for (int nt2 = 0; nt2 < 4; nt2++) {
        uint32_t off = (uint32_t)((nbase + 16 * nt2 + bn) * ASTR + bk);
        ldsm4(bhb + off, bh[nt2]);
        ldsm4(blb + off, bl[nt2]);
    }
#pragma unroll
    for (int mt = 0; mt < 2; mt++)
#pragma unroll
        for (int nt = 0; nt < 8; nt++) {
            const uint32_t* bhp = &bh[nt >> 1][2 * (nt & 1)];
            const uint32_t* blp = &bl[nt >> 1][2 * (nt & 1)];
            mma16816(acc[mt][nt], ah[mt], bhp);
            mma16816(acc[mt][nt], ah[mt], blp);
            mma16816(acc[mt][nt], al[mt], bhp);
        }
}

// ---- loaders (128 threads) ----
static __device__ __forceinline__ void load_W(uint32_t sb, int slab, int tid) {
    for (int u = tid; u < 2048; u += 128) {
        int isLo = u >> 10, uu = u & 1023, r = uu >> 3, c = uu & 7;
        const unsigned char* g = (isLo ? g_Wl : g_Wh) + slab * 16384;
        CPA(sb + (isLo ? OFF_BL : OFF_BH) + r * ASTR + c * 16, g + r * 128 + c * 16);
    }
}
static __device__ __forceinline__ void load_gather(uint32_t sb, int oh, int ol,
        const int* rows, int koffb, int tid) {
    for (int u = tid; u < 1024; u += 128) {
        int isLo = u >> 9, uu = u & 511, r = uu >> 3, c = uu & 7;
        const unsigned char* g = isLo ? (const unsigned char*)g_nlo : (const unsigned char*)g_nhi;
        CPA(sb + (isLo ? ol : oh) + r * ASTR + c * 16,
            g + (size_t)rows[r] * 256 + koffb + c * 16);
    }
}
static __device__ __forceinline__ void load_f32split(unsigned char* sm, int oh, int ol,
        const float* base, const int* rows, int rbase, int koff, int tid) {
    for (int u = tid; u < 1024; u += 128) {
        int r = u >> 4, c4 = u & 15;
        size_t row = rows ? (size_t)rows[r] : (size_t)(rbase + r);
        float4 v = *(const float4*)(base + row * 128 + koff + c4 * 4);
        uint2 hi, lo;
        hi.x = prmt_hi16(__float_as_uint(v.x), __float_as_uint(v.y));
        hi.y = prmt_hi16(__float_as_uint(v.z), __float_as_uint(v.w));
        lo.x = bf2(v.y - trh(v.y), v.x - trh(v.x));
        lo.y = bf2(v.w - trh(v.w), v.z - trh(v.z));
        *(uint2*)(sm + oh + r * ASTR + c4 * 8) = hi;
        *(uint2*)(sm + ol + r * ASTR + c4 * 8) = lo;
    }
}
// epilogue1: bias + relu + split -> Y (stride YSTR, into A region)
static __device__ __forceinline__ void epi_split(float acc[2][8][4], const float* bias,
        unsigned char* sm, int mrow, int nbase, int lane) {
    const int ra = mrow + (lane >> 2);
    const int cc = nbase + 2 * (lane & 3);
#pragma unroll
    for (int mt = 0; mt < 2; mt++)
#pragma unroll
        for (int nt = 0; nt < 8; nt++) {
            int c = cc + 8 * nt;
            float b0 = __ldg(&bias[c]), b1 = __ldg(&bias[c + 1]);
#pragma unroll
            for (int h = 0; h < 2; h++) {
                int r = ra + 16 * mt + 8 * h;
                float v0 = fmaxf(acc[mt][nt][2 * h]     + b0, 0.f);
                float v1 = fmaxf(acc[mt][nt][2 * h + 1] + b1, 0.f);
                *(uint32_t*)(sm + OFF_AH(0) + r * YSTR + c * 2) =
                    prmt_hi16(__float_as_uint(v0), __float_as_uint(v1));
                *(uint32_t*)(sm + OFF_AL(0) + r * YSTR + c * 2) =
                    bf2(v1 - trh(v1), v0 - trh(v0));
            }
        }
}

// ---- prep kernels ----
__global__ void zero_agg_kernel() {
    size_t stride = (size_t)gridDim.x * blockDim.x * 4;
    for (size_t i = (size_t)(blockIdx.x * blockDim.x + threadIdx.x) * 4;
         i < (size_t)NN * 128; i += stride)
        *(float4*)&g_agg[i] = make_float4(0.f, 0.f, 0.f, 0.f);
}
__global__ void prep_weights_kernel(const float* __restrict__ We1, const float* __restrict__ We2,
                                    const float* __restrict__ Wn1, const float* __restrict__ Wn2) {
    int s = blockIdx.x;
    const float* W; int slab;
    if (s < 6)       { W = We1; slab = s; }
    else if (s < 8)  { W = We2; slab = s - 6; }
    else if (s < 12) { W = Wn1; slab = s - 8; }
    else             { W = Wn2; slab = s - 12; }
    unsigned char* ph = g_Wh + s * 16384;
    unsigned char* pl = g_Wl + s * 16384;
    int k0 = slab * 64;
    for (int p = threadIdx.x; p < 4096; p += blockDim.x) {
        int n = p >> 5, kk = (p & 31) << 1;
        float x0 = W[(size_t)(k0 + kk) * 128 + n];
        float x1 = W[(size_t)(k0 + kk + 1) * 128 + n];
        *(uint32_t*)(ph + n * 128 + kk * 2) = prmt_hi16(__float_as_uint(x0), __float_as_uint(x1));
        *(uint32_t*)(pl + n * 128 + kk * 2) = bf2(x1 - trh(x1), x0 - trh(x0));
    }
}
__global__ void prep_node_kernel(const float* __restrict__ node_h) {
    size_t i = (size_t)blockIdx.x * blockDim.x + threadIdx.x;
    if (i >= (size_t)NN * 32) return;
    float4 v = ((const float4*)node_h)[i];
    uint2 hi, lo;
    hi.x = prmt_hi16(__float_as_uint(v.x), __float_as_uint(v.y));
    hi.y = prmt_hi16(__float_as_uint(v.z), __float_as_uint(v.w));
    lo.x = bf2(v.y - trh(v.y), v.x - trh(v.x));
    lo.y = bf2(v.w - trh(v.w), v.z - trh(v.z));
    ((uint2*)g_nhi)[i] = hi;
    ((uint2*)g_nlo)[i] = lo;
}

// ---- edge kernel: 64 edges x 128 cols, 128 threads, 3 CTAs/SM ----
__global__ __launch_bounds__(128, 3)
void edge_kernel(const float* __restrict__ edge_h,
                 const int* __restrict__ src, const int* __restrict__ dst,
                 const float* __restrict__ be1, const float* __restrict__ be2) {
    extern __shared__ __align__(1024) unsigned char sm[];
    const uint32_t sb = smem_u32(sm);
    const int tid = threadIdx.x, wid = tid >> 5, lane = tid & 31;
    const int ebase = blockIdx.x << 6;
    const int mrow = (wid >> 1) << 5;     // 0,32
    const int nbase = (wid & 1) << 6;     // 0,64

    int* srcS = (int*)(sm + OFF_ROWS);
    int* dstS = (int*)(sm + OFF_DST);
    if (tid < 64) { srcS[tid] = src[ebase + tid]; dstS[tid] = dst[ebase + tid]; }
    __syncthreads();

    // prologue: slab0 (src k0) + W0, slab1 (src k64)
    load_gather(sb, OFF_AH(0), OFF_AL(0), srcS, 0, tid);
    load_W(sb, 0, tid);
    load_gather(sb, OFF_AH(1), OFF_AL(1), srcS, 128, tid);
    CPC();

    float acc[2][8][4]; ZACC(acc);
    CPW(0);
    __syncthreads();
    // slabs: 0 src k0, 1 src k64, 2 dst k0, 3 dst k64, 4 eh k0, 5 eh k64
#pragma unroll 1
    for (int s = 0; s < 6; s++) {
        const int b = s & 1;
        for (int c = 0; c < 4; c++)
            mma_chunk(sb + OFF_AH(b), sb + OFF_AL(b), ASTR, sb + OFF_BH, sb + OFF_BL,
                      mrow, nbase, c * 32, c * 32, lane, acc);
        __syncthreads();
        if (s < 5) {
            int nx = s + 2;
            if (nx == 2)      load_gather(sb, OFF_AH(b), OFF_AL(b), dstS, 0, tid);
            else if (nx == 3) load_gather(sb, OFF_AH(b), OFF_AL(b), dstS, 128, tid);
            else if (nx == 4) load_f32split(sm, OFF_AH(b), OFF_AL(b), edge_h, nullptr, ebase, 0, tid);
            else if (nx == 5) load_f32split(sm, OFF_AH(b), OFF_AL(b), edge_h, nullptr, ebase, 64, tid);
            load_W(sb, s + 1, tid);
            CPC(); CPW(0);
            __syncthreads();
        }
    }

    // epilogue1 -> Y, then GEMM2 with We2 (slabs 6,7 through single B)
    load_W(sb, 6, tid); CPC();
    epi_split(acc, be1, sm, mrow, nbase, lane);
    ZACC(acc);
    CPW(0);
    __syncthreads();
    for (int c = 0; c < 4; c++)
        mma_chunk(sb + OFF_AH(0), sb + OFF_AL(0), YSTR, sb + OFF_BH, sb + OFF_BL,
                  mrow, nbase, c * 32, c * 32, lane, acc);
    __syncthreads();
    load_W(sb, 7, tid); CPC(); CPW(0);
    __syncthreads();
    for (int c = 0; c < 4; c++)
        mma_chunk(sb + OFF_AH(0), sb + OFF_AL(0), YSTR, sb + OFF_BH, sb + OFF_BL,
                  mrow, nbase, (4 + c) * 32, c * 32, lane, acc);

    // epilogue2: + be2, scatter-add
    const int ra = mrow + (lane >> 2);
    const int cc = nbase + 2 * (lane & 3);
#pragma unroll
    for (int mt = 0; mt < 2; mt++)
#pragma unroll
        for (int h = 0; h < 2; h++) {
            int r = ra + 16 * mt + 8 * h;
            float* gp = g_agg + (size_t)dstS[r] * 128;
#pragma unroll
            for (int nt = 0; nt < 8; nt++) {
                int c = cc + 8 * nt;
                atomicAdd(gp + c,     acc[mt][nt][2 * h]     + __ldg(&be2[c]));
                atomicAdd(gp + c + 1, acc[mt][nt][2 * h + 1] + __ldg(&be2[c + 1]));
            }
        }
}

// ---- node kernel: 64 nodes x 128 cols, K=256 = [agg | node_h] ----
__global__ __launch_bounds__(128, 3)
void node_kernel(const float* __restrict__ bn1, const float* __restrict__ bn2,
                 float* __restrict__ out) {
    extern __shared__ __align__(1024) unsigned char sm[];
    const uint32_t sb = smem_u32(sm);
    const int tid = threadIdx.x, wid = tid >> 5, lane = tid & 31;
    const int nbase0 = blockIdx.x << 6;
    const int mrow = (wid >> 1) << 5;
    const int nbase = (wid & 1) << 6;

    int* rowsS = (int*)(sm + OFF_ROWS);
    if (tid < 64) { int n = nbase0 + tid; if (n >= NN) n = NN - 1; rowsS[tid] = n; }
    __syncthreads();

    // slabs: 0 agg k0 (f32split), 1 agg k64 (f32split), 2 node k0, 3 node k64
    load_W(sb, 8, tid); CPC();
    load_f32split(sm, OFF_AH(0), OFF_AL(0), g_agg, rowsS, 0, 0, tid);
    load_f32split(sm, OFF_AH(1), OFF_AL(1), g_agg, rowsS, 0, 64, tid);

    float acc[2][8][4]; ZACC(acc);
    CPW(0);
    __syncthreads();
#pragma unroll 1
    for (int s = 0; s < 4; s++) {
        const int b = s & 1;
        for (int c = 0; c < 4; c++)
            mma_chunk(sb + OFF_AH(b), sb + OFF_AL(b), ASTR, sb + OFF_BH, sb + OFF_BL,
                      mrow, nbase, c * 32, c * 32, lane, acc);
        __syncthreads();
        if (s < 3) {
            int nx = s + 2;
            if (nx == 2)      load_gather(sb, OFF_AH(b), OFF_AL(b), rowsS, 0, tid);
            else if (nx == 3) load_gather(sb, OFF_AH(b), OFF_AL(b), rowsS, 128, tid);
            load_W(sb, 9 + s, tid);
            CPC(); CPW(0);
            __syncthreads();
        }
    }

    load_W(sb, 12, tid); CPC();
    epi_split(acc, bn1, sm, mrow, nbase, lane);
    ZACC(acc);
    CPW(0);
    __syncthreads();
    for (int c = 0; c < 4; c++)
        mma_chunk(sb + OFF_AH(0), sb + OFF_AL(0), YSTR, sb + OFF_BH, sb + OFF_BL,
                  mrow, nbase, c * 32, c * 32, lane, acc);
    __syncthreads();
    load_W(sb, 13, tid); CPC(); CPW(0);
    __syncthreads();
    for (int c = 0; c < 4; c++)
        mma_chunk(sb + OFF_AH(0), sb + OFF_AL(0), YSTR, sb + OFF_BH, sb + OFF_BL,
                  mrow, nbase, (4 + c) * 32, c * 32, lane, acc);

    const int ra = mrow + (lane >> 2);
    const int cc = nbase + 2 * (lane & 3);
#pragma unroll
    for (int mt = 0; mt < 2; mt++)
#pragma unroll
        for (int h = 0; h < 2; h++) {
            int r = ra + 16 * mt + 8 * h;
            int n = nbase0 + r;
            if (n < NN) {
#pragma unroll
                for (int nt = 0; nt < 8; nt++) {
                    int c = cc + 8 * nt;
                    *(float2*)(out + (size_t)n * 128 + c) =
                        make_float2(acc[mt][nt][2 * h]     + __ldg(&bn2[c]),
                                    acc[mt][nt][2 * h + 1] + __ldg(&bn2[c + 1]));
                }
            }
        }
}

extern "C" void kernel_launch(void* const* d_in, const int* in_sizes, int n_in,
                              void* d_out, int out_size) {
    const float* node_h = (const float*)d_in[0];
    const float* edge_h = (const float*)d_in[1];
    const int*   src    = (const int*)d_in[2];
    const int*   dst    = (const int*)d_in[3];
    const float* We1    = (const float*)d_in[4];
    const float* be1    = (const float*)d_in[5];
    const float* We2    = (const float*)d_in[6];
    const float* be2    = (const float*)d_in[7];
    const float* Wn1    = (const float*)d_in[8];
    const float* bn1    = (const float*)d_in[9];
    const float* Wn2    = (const float*)d_in[10];
    const float* bn2    = (const float*)d_in[11];
    float* out = (float*)d_out;

    cudaFuncSetAttribute(edge_kernel, cudaFuncAttributeMaxDynamicSharedMemorySize, SM_BYTES);
    cudaFuncSetAttribute(node_kernel, cudaFuncAttributeMaxDynamicSharedMemorySize, SM_BYTES);

    zero_agg_kernel<<<1024, 256>>>();
    prep_weights_kernel<<<14, 256>>>(We1, We2, Wn1, Wn2);
    prep_node_kernel<<<6250, 256>>>(node_h);
    edge_kernel<<<NE / 64, 128, SM_BYTES>>>(edge_h, src, dst, be1, be2);
    node_kernel<<<(NN + 63) / 64, 128, SM_BYTES>>>(bn1, bn2, out);
}

// round 9
// speedup vs baseline: 1.8279x; 1.1244x over previous
#include <cuda_runtime.h>
#include <cstdint>

#define NN 50000
#define NE 640000

__device__ float g_agg[(size_t)NN * 128];
__device__ float g_U[(size_t)NN * 128];    // node_h @ We1[0:128]
__device__ float g_V[(size_t)NN * 128];    // node_h @ We1[128:256]
__device__ float g_P[(size_t)NN * 128];    // node_h @ Wn1[128:256]
// weight slab images, transposed [128 N x 64 K] bf16 row-major (128B/row):
// We1:0-5, We2:6-7, Wn1:8-11, Wn2:12-13
__device__ __align__(16) unsigned char g_Wh[14 * 16384];
__device__ __align__(16) unsigned char g_Wl[14 * 16384];

static __device__ __forceinline__ uint32_t smem_u32(const void* p) {
    uint32_t a;
    asm("{ .reg .u64 t; cvta.to.shared.u64 t, %1; cvt.u32.u64 %0, t; }" : "=r"(a) : "l"(p));
    return a;
}
static __device__ __forceinline__ uint32_t prmt_hi16(uint32_t a, uint32_t b) {
    uint32_t r; asm("prmt.b32 %0,%1,%2,0x7632;" : "=r"(r) : "r"(a), "r"(b)); return r;
}
static __device__ __forceinline__ float trh(float x) {
    return __uint_as_float(__float_as_uint(x) & 0xFFFF0000u);
}
static __device__ __forceinline__ uint32_t bf2(float hi_, float lo_) {
    uint32_t r; asm("cvt.rn.bf16x2.f32 %0,%1,%2;" : "=r"(r) : "f"(hi_), "f"(lo_)); return r;
}

#define CPA(dst, src) asm volatile("cp.async.ca.shared.global [%0], [%1], 16;" :: "r"(dst), "l"(src))
#define CPC()         asm volatile("cp.async.commit_group;" ::: "memory")
#define CPW(n)        asm volatile("cp.async.wait_group %0;" :: "n"(n) : "memory")

static __device__ __forceinline__ void ldsm4(uint32_t addr, uint32_t* r) {
    asm volatile("ldmatrix.sync.aligned.m8n8.x4.shared.b16 {%0,%1,%2,%3}, [%4];"
                 : "=r"(r[0]), "=r"(r[1]), "=r"(r[2]), "=r"(r[3]) : "r"(addr));
}
static __device__ __forceinline__ void mma16816(float* d, const uint32_t* a, const uint32_t* b) {
    asm volatile("mma.sync.aligned.m16n8k16.row.col.f32.bf16.bf16.f32 "
                 "{%0,%1,%2,%3},{%4,%5,%6,%7},{%8,%9},{%0,%1,%2,%3};"
                 : "+f"(d[0]), "+f"(d[1]), "+f"(d[2]), "+f"(d[3])
                 : "r"(a[0]), "r"(a[1]), "r"(a[2]), "r"(a[3]), "r"(b[0]), "r"(b[1]));
}

// SMEM: 64-row A tiles (hi/lo, double-buffered) + 128-row B (hi/lo, single)
#define OFF_DST  0
#define OFF_ROWS 256
#define ABUF     9216                     // 64 * 144
#define OFF_AH(b) (2048 + (b) * ABUF)     // AH0,AH1 contiguous (Y hi reuse)
#define OFF_AL(b) (2048 + 2 * ABUF + (b) * ABUF)
#define OFF_BH    (2048 + 4 * ABUF)       // 128 * 144 = 18432
#define OFF_BL    (OFF_BH + 18432)
#define SM_BYTES  (2048 + 4 * ABUF + 2 * 18432)   // 75776
#define ASTR 144
#define YSTR 272

#define ZACC(a) do {                                                   \
    _Pragma("unroll") for (int _m = 0; _m < 2; _m++)                   \
    _Pragma("unroll") for (int _n = 0; _n < 8; _n++)                   \
    _Pragma("unroll") for (int _q = 0; _q < 4; _q++) (a)[_m][_n][_q] = 0.f; } while (0)

// one K=16 chunk, 3-term compensated: 12 LDSM + 48 MMA (warp: 32 rows x 64 cols)
static __device__ __forceinline__ void mma_chunk(
        uint32_t ahb, uint32_t alb, int astride, uint32_t bhb, uint32_t blb,
        int mrow, int nbase, int kb, int bkb, int lane, float acc[2][8][4]) {
    uint32_t ah[2][4], al[2][4], bh[4][4], bl[4][4];
    const int arow = mrow + (lane & 15);
    const int ak   = kb + (lane >> 4) * 16;
#pragma unroll
    for (int mt = 0; mt < 2; mt++) {
        uint32_t off = (uint32_t)((arow + 16 * mt) * astride + ak);
        ldsm4(ahb + off, ah[mt]);
        ldsm4(alb + off, al[mt]);
    }
    const int bn = (lane & 7) + 8 * (lane >> 4);
    const int bk = bkb + ((lane >> 3) & 1) * 16;
#pragma unroll
    for (int nt2 = 0; nt2 < 4; nt2++) {
        uint32_t off = (uint32_t)((nbase + 16 * nt2 + bn) * ASTR + bk);
        ldsm4(bhb + off, bh[nt2]);
        ldsm4(blb + off, bl[nt2]);
    }
#pragma unroll
    for (int mt = 0; mt < 2; mt++)
#pragma unroll
        for (int nt = 0; nt < 8; nt++) {
            const uint32_t* bhp = &bh[nt >> 1][2 * (nt & 1)];
            const uint32_t* blp = &bl[nt >> 1][2 * (nt & 1)];
            mma16816(acc[mt][nt], ah[mt], bhp);
            mma16816(acc[mt][nt], ah[mt], blp);
            mma16816(acc[mt][nt], al[mt], bhp);
        }
}

// ---- loaders (128 threads) ----
static __device__ __forceinline__ void load_W(uint32_t sb, int slab, int tid) {
    for (int u = tid; u < 2048; u += 128) {
        int isLo = u >> 10, uu = u & 1023, r = uu >> 3, c = uu & 7;
        const unsigned char* g = (isLo ? g_Wl : g_Wh) + slab * 16384;
        CPA(sb + (isLo ? OFF_BL : OFF_BH) + r * ASTR + c * 16, g + r * 128 + c * 16);
    }
}
static __device__ __forceinline__ void load_f32split(unsigned char* sm, int oh, int ol,
        const float* base, const int* rows, int rbase, int koff, int tid) {
    for (int u = tid; u < 1024; u += 128) {
        int r = u >> 4, c4 = u & 15;
        size_t row = rows ? (size_t)rows[r] : (size_t)(rbase + r);
        float4 v = *(const float4*)(base + row * 128 + koff + c4 * 4);
        uint2 hi, lo;
        hi.x = prmt_hi16(__float_as_uint(v.x), __float_as_uint(v.y));
        hi.y = prmt_hi16(__float_as_uint(v.z), __float_as_uint(v.w));
        lo.x = bf2(v.y - trh(v.y), v.x - trh(v.x));
        lo.y = bf2(v.w - trh(v.w), v.z - trh(v.z));
        *(uint2*)(sm + oh + r * ASTR + c4 * 8) = hi;
        *(uint2*)(sm + ol + r * ASTR + c4 * 8) = lo;
    }
}

// ---- prep kernels ----
__global__ void zero_agg_kernel() {
    size_t stride = (size_t)gridDim.x * blockDim.x * 4;
    for (size_t i = (size_t)(blockIdx.x * blockDim.x + threadIdx.x) * 4;
         i < (size_t)NN * 128; i += stride)
        *(float4*)&g_agg[i] = make_float4(0.f, 0.f, 0.f, 0.f);
}
__global__ void prep_weights_kernel(const float* __restrict__ We1, const float* __restrict__ We2,
                                    const float* __restrict__ Wn1, const float* __restrict__ Wn2) {
    int s = blockIdx.x;
    const float* W; int slab;
    if (s < 6)       { W = We1; slab = s; }
    else if (s < 8)  { W = We2; slab = s - 6; }
    else if (s < 12) { W = Wn1; slab = s - 8; }
    else             { W = Wn2; slab = s - 12; }
    unsigned char* ph = g_Wh + s * 16384;
    unsigned char* pl = g_Wl + s * 16384;
    int k0 = slab * 64;
    for (int p = threadIdx.x; p < 4096; p += blockDim.x) {
        int n = p >> 5, kk = (p & 31) << 1;
        float x0 = W[(size_t)(k0 + kk) * 128 + n];
        float x1 = W[(size_t)(k0 + kk + 1) * 128 + n];
        *(uint32_t*)(ph + n * 128 + kk * 2) = prmt_hi16(__float_as_uint(x0), __float_as_uint(x1));
        *(uint32_t*)(pl + n * 128 + kk * 2) = bf2(x1 - trh(x1), x0 - trh(x0));
    }
}

// ---- precompute: U = nh@We1[0:128], V = nh@We1[128:256], P = nh@Wn1[128:256] ----
__global__ __launch_bounds__(128, 3)
void precompute_kernel(const float* __restrict__ node_h) {
    extern __shared__ __align__(1024) unsigned char sm[];
    const uint32_t sb = smem_u32(sm);
    const int tid = threadIdx.x, wid = tid >> 5, lane = tid & 31;
    const int nbase0 = blockIdx.x << 6;
    const int mrow = (wid >> 1) << 5;
    const int nbase = (wid & 1) << 6;

    int* rowsS = (int*)(sm + OFF_ROWS);
    if (tid < 64) { int n = nbase0 + tid; if (n >= NN) n = NN - 1; rowsS[tid] = n; }
    __syncthreads();

    load_f32split(sm, OFF_AH(0), OFF_AL(0), node_h, rowsS, 0, 0, tid);
    load_f32split(sm, OFF_AH(1), OFF_AL(1), node_h, rowsS, 0, 64, tid);
    __syncthreads();

    const int ra = mrow + (lane >> 2);
    const int cc = nbase + 2 * (lane & 3);
    const int w0[3] = {0, 2, 10}, w1[3] = {1, 3, 11};
    float* outs[3] = {g_U, g_V, g_P};
#pragma unroll 1
    for (int t = 0; t < 3; t++) {
        float acc[2][8][4]; ZACC(acc);
        load_W(sb, w0[t], tid); CPC(); CPW(0);
        __syncthreads();
        for (int c = 0; c < 4; c++)
            mma_chunk(sb + OFF_AH(0), sb + OFF_AL(0), ASTR, sb + OFF_BH, sb + OFF_BL,
                      mrow, nbase, c * 32, c * 32, lane, acc);
        __syncthreads();
        load_W(sb, w1[t], tid); CPC(); CPW(0);
        __syncthreads();
        for (int c = 0; c < 4; c++)
            mma_chunk(sb + OFF_AH(1), sb + OFF_AL(1), ASTR, sb + OFF_BH, sb + OFF_BL,
                      mrow, nbase, c * 32, c * 32, lane, acc);
        __syncthreads();
        float* op = outs[t];
#pragma unroll
        for (int mt = 0; mt < 2; mt++)
#pragma unroll
            for (int h = 0; h < 2; h++) {
                int r = ra + 16 * mt + 8 * h;
                int n = nbase0 + r;
                if (n < NN) {
#pragma unroll
                    for (int nt = 0; nt < 8; nt++) {
                        int c = cc + 8 * nt;
                        *(float2*)(op + (size_t)n * 128 + c) =
                            make_float2(acc[mt][nt][2 * h], acc[mt][nt][2 * h + 1]);
                    }
                }
            }
    }
}

// ---- edge kernel: 64 edges x 128 cols, GEMM1 = e@Wc only, U/V in epilogue ----
__global__ __launch_bounds__(128, 3)
void edge_kernel(const float* __restrict__ edge_h,
                 const int* __restrict__ src, const int* __restrict__ dst,
                 const float* __restrict__ be1, const float* __restrict__ be2) {
    extern __shared__ __align__(1024) unsigned char sm[];
    const uint32_t sb = smem_u32(sm);
    const int tid = threadIdx.x, wid = tid >> 5, lane = tid & 31;
    const int ebase = blockIdx.x << 6;
    const int mrow = (wid >> 1) << 5;
    const int nbase = (wid & 1) << 6;

    int* srcS = (int*)(sm + OFF_ROWS);
    int* dstS = (int*)(sm + OFF_DST);
    if (tid < 64) { srcS[tid] = src[ebase + tid]; dstS[tid] = dst[ebase + tid]; }

    // both edge_h slabs split up-front (A double-buffered), W slab 4 via cp.async
    load_W(sb, 4, tid); CPC();
    load_f32split(sm, OFF_AH(0), OFF_AL(0), edge_h, nullptr, ebase, 0, tid);
    load_f32split(sm, OFF_AH(1), OFF_AL(1), edge_h, nullptr, ebase, 64, tid);

    float acc[2][8][4]; ZACC(acc);
    CPW(0);
    __syncthreads();
    for (int c = 0; c < 4; c++)
        mma_chunk(sb + OFF_AH(0), sb + OFF_AL(0), ASTR, sb + OFF_BH, sb + OFF_BL,
                  mrow, nbase, c * 32, c * 32, lane, acc);
    __syncthreads();
    load_W(sb, 5, tid); CPC(); CPW(0);
    __syncthreads();
    for (int c = 0; c < 4; c++)
        mma_chunk(sb + OFF_AH(1), sb + OFF_AL(1), ASTR, sb + OFF_BH, sb + OFF_BL,
                  mrow, nbase, c * 32, c * 32, lane, acc);
    __syncthreads();
    load_W(sb, 6, tid); CPC();     // We2 k0 overlaps the epilogue

    // epilogue1: acc + U[src] + V[dst] + be1 -> relu -> split -> Y
    const int ra = mrow + (lane >> 2);
    const int cc = nbase + 2 * (lane & 3);
#pragma unroll
    for (int mt = 0; mt < 2; mt++)
#pragma unroll
        for (int h = 0; h < 2; h++) {
            int r = ra + 16 * mt + 8 * h;
            const float* up = g_U + (size_t)srcS[r] * 128;
            const float* vp = g_V + (size_t)dstS[r] * 128;
#pragma unroll
            for (int nt = 0; nt < 8; nt++) {
                int c = cc + 8 * nt;
                float2 u = __ldg((const float2*)(up + c));
                float2 v = __ldg((const float2*)(vp + c));
                float v0 = fmaxf(acc[mt][nt][2 * h]     + u.x + v.x + __ldg(&be1[c]),     0.f);
                float v1 = fmaxf(acc[mt][nt][2 * h + 1] + u.y + v.y + __ldg(&be1[c + 1]), 0.f);
                *(uint32_t*)(sm + OFF_AH(0) + r * YSTR + c * 2) =
                    prmt_hi16(__float_as_uint(v0), __float_as_uint(v1));
                *(uint32_t*)(sm + OFF_AL(0) + r * YSTR + c * 2) =
                    bf2(v1 - trh(v1), v0 - trh(v0));
            }
        }
    ZACC(acc);
    CPW(0);
    __syncthreads();
    for (int c = 0; c < 4; c++)
        mma_chunk(sb + OFF_AH(0), sb + OFF_AL(0), YSTR, sb + OFF_BH, sb + OFF_BL,
                  mrow, nbase, c * 32, c * 32, lane, acc);
    __syncthreads();
    load_W(sb, 7, tid); CPC(); CPW(0);
    __syncthreads();
    for (int c = 0; c < 4; c++)
        mma_chunk(sb + OFF_AH(0), sb + OFF_AL(0), YSTR, sb + OFF_BH, sb + OFF_BL,
                  mrow, nbase, (4 + c) * 32, c * 32, lane, acc);

    // epilogue2: + be2, scatter-add
#pragma unroll
    for (int mt = 0; mt < 2; mt++)
#pragma unroll
        for (int h = 0; h < 2; h++) {
            int r = ra + 16 * mt + 8 * h;
            float* gp = g_agg + (size_t)dstS[r] * 128;
#pragma unroll
            for (int nt = 0; nt < 8; nt++) {
                int c = cc + 8 * nt;
                atomicAdd(gp + c,     acc[mt][nt][2 * h]     + __ldg(&be2[c]));
                atomicAdd(gp + c + 1, acc[mt][nt][2 * h + 1] + __ldg(&be2[c + 1]));
            }
        }
}

// ---- node kernel: GEMM1 = agg@Wn1[0:128] only, P in epilogue ----
__global__ __launch_bounds__(128, 3)
void node_kernel(const float* __restrict__ bn1, const float* __restrict__ bn2,
                 float* __restrict__ out) {
    extern __shared__ __align__(1024) unsigned char sm[];
    const uint32_t sb = smem_u32(sm);
    const int tid = threadIdx.x, wid = tid >> 5, lane = tid & 31;
    const int nbase0 = blockIdx.x << 6;
    const int mrow = (wid >> 1) << 5;
    const int nbase = (wid & 1) << 6;

    int* rowsS = (int*)(sm + OFF_ROWS);
    if (tid < 64) { int n = nbase0 + tid; if (n >= NN) n = NN - 1; rowsS[tid] = n; }
    __syncthreads();

    load_W(sb, 8, tid); CPC();
    load_f32split(sm, OFF_AH(0), OFF_AL(0), g_agg, rowsS, 0, 0, tid);
    load_f32split(sm, OFF_AH(1), OFF_AL(1), g_agg, rowsS, 0, 64, tid);

    float acc[2][8][4]; ZACC(acc);
    CPW(0);
    __syncthreads();
    for (int c = 0; c < 4; c++)
        mma_chunk(sb + OFF_AH(0), sb + OFF_AL(0), ASTR, sb + OFF_BH, sb + OFF_BL,
                  mrow, nbase, c * 32, c * 32, lane, acc);
    __syncthreads();
    load_W(sb, 9, tid); CPC(); CPW(0);
    __syncthreads();
    for (int c = 0; c < 4; c++)
        mma_chunk(sb + OFF_AH(1), sb + OFF_AL(1), ASTR, sb + OFF_BH, sb + OFF_BL,
                  mrow, nbase, c * 32, c * 32, lane, acc);
    __syncthreads();
    load_W(sb, 12, tid); CPC();

    const int ra = mrow + (lane >> 2);
    const int cc = nbase + 2 * (lane & 3);
#pragma unroll
    for (int mt = 0; mt < 2; mt++)
#pragma unroll
        for (int h = 0; h < 2; h++) {
            int r = ra + 16 * mt + 8 * h;
            const float* pp = g_P + (size_t)rowsS[r] * 128;
#pragma unroll
            for (int nt = 0; nt < 8; nt++) {
                int c = cc + 8 * nt;
                float2 p = __ldg((const float2*)(pp + c));
                float v0 = fmaxf(acc[mt][nt][2 * h]     + p.x + __ldg(&bn1[c]),     0.f);
                float v1 = fmaxf(acc[mt][nt][2 * h + 1] + p.y + __ldg(&bn1[c + 1]), 0.f);
                *(uint32_t*)(sm + OFF_AH(0) + r * YSTR + c * 2) =
                    prmt_hi16(__float_as_uint(v0), __float_as_uint(v1));
                *(uint32_t*)(sm + OFF_AL(0) + r * YSTR + c * 2) =
                    bf2(v1 - trh(v1), v0 - trh(v0));
            }
        }
    ZACC(acc);
    CPW(0);
    __syncthreads();
    for (int c = 0; c < 4; c++)
        mma_chunk(sb + OFF_AH(0), sb + OFF_AL(0), YSTR, sb + OFF_BH, sb + OFF_BL,
                  mrow, nbase, c * 32, c * 32, lane, acc);
    __syncthreads();
    load_W(sb, 13, tid); CPC(); CPW(0);
    __syncthreads();
    for (int c = 0; c < 4; c++)
        mma_chunk(sb + OFF_AH(0), sb + OFF_AL(0), YSTR, sb + OFF_BH, sb + OFF_BL,
                  mrow, nbase, (4 + c) * 32, c * 32, lane, acc);

#pragma unroll
    for (int mt = 0; mt < 2; mt++)
#pragma unroll
        for (int h = 0; h < 2; h++) {
            int r = ra + 16 * mt + 8 * h;
            int n = nbase0 + r;
            if (n < NN) {
#pragma unroll
                for (int nt = 0; nt < 8; nt++) {
                    int c = cc + 8 * nt;
                    *(float2*)(out + (size_t)n * 128 + c) =
                        make_float2(acc[mt][nt][2 * h]     + __ldg(&bn2[c]),
                                    acc[mt][nt][2 * h + 1] + __ldg(&bn2[c + 1]));
                }
            }
        }
}

extern "C" void kernel_launch(void* const* d_in, const int* in_sizes, int n_in,
                              void* d_out, int out_size) {
    const float* node_h = (const float*)d_in[0];
    const float* edge_h = (const float*)d_in[1];
    const int*   src    = (const int*)d_in[2];
    const int*   dst    = (const int*)d_in[3];
    const float* We1    = (const float*)d_in[4];
    const float* be1    = (const float*)d_in[5];
    const float* We2    = (const float*)d_in[6];
    const float* be2    = (const float*)d_in[7];
    const float* Wn1    = (const float*)d_in[8];
    const float* bn1    = (const float*)d_in[9];
    const float* Wn2    = (const float*)d_in[10];
    const float* bn2    = (const float*)d_in[11];
    float* out = (float*)d_out;

    cudaFuncSetAttribute(precompute_kernel, cudaFuncAttributeMaxDynamicSharedMemorySize, SM_BYTES);
    cudaFuncSetAttribute(edge_kernel, cudaFuncAttributeMaxDynamicSharedMemorySize, SM_BYTES);
    cudaFuncSetAttribute(node_kernel, cudaFuncAttributeMaxDynamicSharedMemorySize, SM_BYTES);

    zero_agg_kernel<<<1024, 256>>>();
    prep_weights_kernel<<<14, 256>>>(We1, We2, Wn1, Wn2);
    precompute_kernel<<<(NN + 63) / 64, 128, SM_BYTES>>>(node_h);
    edge_kernel<<<NE / 64, 128, SM_BYTES>>>(edge_h, src, dst, be1, be2);
    node_kernel<<<(NN + 63) / 64, 128, SM_BYTES>>>(bn1, bn2, out);
}